// round 1
// baseline (speedup 1.0000x reference)
#include <cuda_runtime.h>

// Problem constants
#define Bsz    2
#define Sq     2048
#define Dm     512
#define Hn     8
#define DH     64
#define BHN    (Bsz*Hn)        // 16
#define MROWS  (Bsz*Sq)        // 4096

// Scratch (device globals — no allocation allowed in kernel_launch)
__device__ float g_qp[BHN * Sq * DH];                 // [b,h,s,dh]  8 MB
__device__ float g_kp[BHN * Sq * DH];
__device__ float g_vp[BHN * Sq * DH];
__device__ float g_scores[(size_t)BHN * Sq * Sq];     // 256 MB
__device__ float g_ctx[MROWS * Dm];                   // merged-head context, 8 MB

// ---------------------------------------------------------------------------
// Kernel 1: fused QKV projection.  C = X @ W^T + b, written in [b,h,s,dh].
// X: [4096,512] row-major (K contiguous), W: [512,512] row-major (K contiguous).
// Tile 64x64, BK=16, 256 threads, 4x4 per-thread microtile.
// grid = (N/64=8, M/64=64, 3)  z selects q/k/v source.
// ---------------------------------------------------------------------------
__global__ __launch_bounds__(256)
void proj_kernel(const float* __restrict__ q, const float* __restrict__ k,
                 const float* __restrict__ v, const float* __restrict__ W,
                 const float* __restrict__ bias)
{
    __shared__ float As[16][64];
    __shared__ float Bs[16][64];

    const float* X = (blockIdx.z == 0) ? q : (blockIdx.z == 1) ? k : v;
    float* out = (blockIdx.z == 0) ? g_qp : (blockIdx.z == 1) ? g_kp : g_vp;

    const int m0 = blockIdx.y * 64;
    const int n0 = blockIdx.x * 64;
    const int tid = threadIdx.x;
    const int tx = tid & 15, ty = tid >> 4;
    const int lm = tid >> 2, lk4 = (tid & 3) * 4;

    float acc[4][4] = {};

    for (int k0 = 0; k0 < Dm; k0 += 16) {
        float4 va = *(const float4*)(X + (size_t)(m0 + lm) * Dm + k0 + lk4);
        float4 vb = *(const float4*)(W + (size_t)(n0 + lm) * Dm + k0 + lk4);
        As[lk4 + 0][lm] = va.x; As[lk4 + 1][lm] = va.y;
        As[lk4 + 2][lm] = va.z; As[lk4 + 3][lm] = va.w;
        Bs[lk4 + 0][lm] = vb.x; Bs[lk4 + 1][lm] = vb.y;
        Bs[lk4 + 2][lm] = vb.z; Bs[lk4 + 3][lm] = vb.w;
        __syncthreads();
#pragma unroll
        for (int kk = 0; kk < 16; ++kk) {
            float4 a = *(const float4*)&As[kk][ty * 4];
            float4 b = *(const float4*)&Bs[kk][tx * 4];
            acc[0][0] += a.x * b.x; acc[0][1] += a.x * b.y; acc[0][2] += a.x * b.z; acc[0][3] += a.x * b.w;
            acc[1][0] += a.y * b.x; acc[1][1] += a.y * b.y; acc[1][2] += a.y * b.z; acc[1][3] += a.y * b.w;
            acc[2][0] += a.z * b.x; acc[2][1] += a.z * b.y; acc[2][2] += a.z * b.z; acc[2][3] += a.z * b.w;
            acc[3][0] += a.w * b.x; acc[3][1] += a.w * b.y; acc[3][2] += a.w * b.z; acc[3][3] += a.w * b.w;
        }
        __syncthreads();
    }

#pragma unroll
    for (int i = 0; i < 4; ++i) {
#pragma unroll
        for (int j = 0; j < 4; ++j) {
            int m = m0 + ty * 4 + i;       // b*2048+s
            int n = n0 + tx * 4 + j;       // h*64+d
            int b_ = m >> 11, s = m & 2047;
            int h  = n >> 6,  d = n & 63;
            out[(((size_t)(b_ * Hn + h) * Sq) + s) * DH + d] = acc[i][j] + bias[n];
        }
    }
}

// ---------------------------------------------------------------------------
// Kernel 2: scores = scale * Q @ K^T per (b,h).  K-dim = 64.
// grid = (32, 32, 16)
// ---------------------------------------------------------------------------
__global__ __launch_bounds__(256)
void qk_kernel()
{
    __shared__ float As[16][64];
    __shared__ float Bs[16][64];

    const int z = blockIdx.z;
    const float* Q  = g_qp + (size_t)z * Sq * DH;
    const float* Kp = g_kp + (size_t)z * Sq * DH;
    float* Sc = g_scores + (size_t)z * Sq * Sq;

    const int m0 = blockIdx.y * 64;
    const int n0 = blockIdx.x * 64;
    const int tid = threadIdx.x;
    const int tx = tid & 15, ty = tid >> 4;
    const int lm = tid >> 2, lk4 = (tid & 3) * 4;

    float acc[4][4] = {};

    for (int k0 = 0; k0 < DH; k0 += 16) {
        float4 va = *(const float4*)(Q  + (size_t)(m0 + lm) * DH + k0 + lk4);
        float4 vb = *(const float4*)(Kp + (size_t)(n0 + lm) * DH + k0 + lk4);
        As[lk4 + 0][lm] = va.x; As[lk4 + 1][lm] = va.y;
        As[lk4 + 2][lm] = va.z; As[lk4 + 3][lm] = va.w;
        Bs[lk4 + 0][lm] = vb.x; Bs[lk4 + 1][lm] = vb.y;
        Bs[lk4 + 2][lm] = vb.z; Bs[lk4 + 3][lm] = vb.w;
        __syncthreads();
#pragma unroll
        for (int kk = 0; kk < 16; ++kk) {
            float4 a = *(const float4*)&As[kk][ty * 4];
            float4 b = *(const float4*)&Bs[kk][tx * 4];
            acc[0][0] += a.x * b.x; acc[0][1] += a.x * b.y; acc[0][2] += a.x * b.z; acc[0][3] += a.x * b.w;
            acc[1][0] += a.y * b.x; acc[1][1] += a.y * b.y; acc[1][2] += a.y * b.z; acc[1][3] += a.y * b.w;
            acc[2][0] += a.z * b.x; acc[2][1] += a.z * b.y; acc[2][2] += a.z * b.z; acc[2][3] += a.z * b.w;
            acc[3][0] += a.w * b.x; acc[3][1] += a.w * b.y; acc[3][2] += a.w * b.z; acc[3][3] += a.w * b.w;
        }
        __syncthreads();
    }

    const float scale = 0.125f;   // 1/sqrt(64)
#pragma unroll
    for (int i = 0; i < 4; ++i)
#pragma unroll
        for (int j = 0; j < 4; ++j)
            Sc[(size_t)(m0 + ty * 4 + i) * Sq + (n0 + tx * 4 + j)] = acc[i][j] * scale;
}

// ---------------------------------------------------------------------------
// Kernel 3: row softmax over 2048 elements.  One block (256 thr) per row,
// 8 values per thread kept in registers.  grid = 32768.
// ---------------------------------------------------------------------------
__global__ __launch_bounds__(256)
void softmax_kernel()
{
    float* p = g_scores + (size_t)blockIdx.x * Sq;
    const int tid = threadIdx.x;

    float vals[8];
    float lmax = -1e30f;
#pragma unroll
    for (int i = 0; i < 8; ++i) {
        vals[i] = p[tid + i * 256];
        lmax = fmaxf(lmax, vals[i]);
    }
#pragma unroll
    for (int o = 16; o; o >>= 1) lmax = fmaxf(lmax, __shfl_xor_sync(0xffffffffu, lmax, o));

    __shared__ float redm[8];
    __shared__ float reds[8];
    if ((tid & 31) == 0) redm[tid >> 5] = lmax;
    __syncthreads();
    float rmax = redm[0];
#pragma unroll
    for (int i = 1; i < 8; ++i) rmax = fmaxf(rmax, redm[i]);

    float lsum = 0.f;
#pragma unroll
    for (int i = 0; i < 8; ++i) {
        vals[i] = __expf(vals[i] - rmax);
        lsum += vals[i];
    }
#pragma unroll
    for (int o = 16; o; o >>= 1) lsum += __shfl_xor_sync(0xffffffffu, lsum, o);
    if ((tid & 31) == 0) reds[tid >> 5] = lsum;
    __syncthreads();
    float rsum = 0.f;
#pragma unroll
    for (int i = 0; i < 8; ++i) rsum += reds[i];

    const float inv = 1.0f / rsum;
#pragma unroll
    for (int i = 0; i < 8; ++i) p[tid + i * 256] = vals[i] * inv;
}

// ---------------------------------------------------------------------------
// Kernel 4: ctx = att @ V per (b,h), written merged-head [b,s,h*64+d].
// A: [2048,2048] (k contiguous), V: [2048,64] (d contiguous). BN=64=dh.
// grid = (1, 32, 16)
// ---------------------------------------------------------------------------
__global__ __launch_bounds__(256)
void av_kernel()
{
    __shared__ float As[16][64];
    __shared__ float Bs[16][64];

    const int z = blockIdx.z;
    const float* A = g_scores + (size_t)z * Sq * Sq;
    const float* V = g_vp + (size_t)z * Sq * DH;

    const int m0 = blockIdx.y * 64;
    const int tid = threadIdx.x;
    const int tx = tid & 15, ty = tid >> 4;
    const int lm  = tid >> 2,  lk4 = (tid & 3) * 4;   // A-tile loader
    const int lkb = tid >> 4,  ld4 = (tid & 15) * 4;  // V-tile loader

    float acc[4][4] = {};

    for (int k0 = 0; k0 < Sq; k0 += 16) {
        float4 va = *(const float4*)(A + (size_t)(m0 + lm) * Sq + k0 + lk4);
        As[lk4 + 0][lm] = va.x; As[lk4 + 1][lm] = va.y;
        As[lk4 + 2][lm] = va.z; As[lk4 + 3][lm] = va.w;
        float4 vb = *(const float4*)(V + (size_t)(k0 + lkb) * DH + ld4);
        *(float4*)&Bs[lkb][ld4] = vb;
        __syncthreads();
#pragma unroll
        for (int kk = 0; kk < 16; ++kk) {
            float4 a = *(const float4*)&As[kk][ty * 4];
            float4 b = *(const float4*)&Bs[kk][tx * 4];
            acc[0][0] += a.x * b.x; acc[0][1] += a.x * b.y; acc[0][2] += a.x * b.z; acc[0][3] += a.x * b.w;
            acc[1][0] += a.y * b.x; acc[1][1] += a.y * b.y; acc[1][2] += a.y * b.z; acc[1][3] += a.y * b.w;
            acc[2][0] += a.z * b.x; acc[2][1] += a.z * b.y; acc[2][2] += a.z * b.z; acc[2][3] += a.z * b.w;
            acc[3][0] += a.w * b.x; acc[3][1] += a.w * b.y; acc[3][2] += a.w * b.z; acc[3][3] += a.w * b.w;
        }
        __syncthreads();
    }

    const int b_ = z >> 3, h = z & 7;
#pragma unroll
    for (int i = 0; i < 4; ++i)
#pragma unroll
        for (int j = 0; j < 4; ++j) {
            int s = m0 + ty * 4 + i;
            int d = tx * 4 + j;
            g_ctx[(size_t)(b_ * Sq + s) * Dm + h * DH + d] = acc[i][j];
        }
}

// ---------------------------------------------------------------------------
// Kernel 5: out = ctx @ Wc^T + bc.  grid = (8, 64)
// ---------------------------------------------------------------------------
__global__ __launch_bounds__(256)
void outproj_kernel(const float* __restrict__ W, const float* __restrict__ bias,
                    float* __restrict__ out)
{
    __shared__ float As[16][64];
    __shared__ float Bs[16][64];

    const int m0 = blockIdx.y * 64;
    const int n0 = blockIdx.x * 64;
    const int tid = threadIdx.x;
    const int tx = tid & 15, ty = tid >> 4;
    const int lm = tid >> 2, lk4 = (tid & 3) * 4;

    float acc[4][4] = {};

    for (int k0 = 0; k0 < Dm; k0 += 16) {
        float4 va = *(const float4*)(g_ctx + (size_t)(m0 + lm) * Dm + k0 + lk4);
        float4 vb = *(const float4*)(W + (size_t)(n0 + lm) * Dm + k0 + lk4);
        As[lk4 + 0][lm] = va.x; As[lk4 + 1][lm] = va.y;
        As[lk4 + 2][lm] = va.z; As[lk4 + 3][lm] = va.w;
        Bs[lk4 + 0][lm] = vb.x; Bs[lk4 + 1][lm] = vb.y;
        Bs[lk4 + 2][lm] = vb.z; Bs[lk4 + 3][lm] = vb.w;
        __syncthreads();
#pragma unroll
        for (int kk = 0; kk < 16; ++kk) {
            float4 a = *(const float4*)&As[kk][ty * 4];
            float4 b = *(const float4*)&Bs[kk][tx * 4];
            acc[0][0] += a.x * b.x; acc[0][1] += a.x * b.y; acc[0][2] += a.x * b.z; acc[0][3] += a.x * b.w;
            acc[1][0] += a.y * b.x; acc[1][1] += a.y * b.y; acc[1][2] += a.y * b.z; acc[1][3] += a.y * b.w;
            acc[2][0] += a.z * b.x; acc[2][1] += a.z * b.y; acc[2][2] += a.z * b.z; acc[2][3] += a.z * b.w;
            acc[3][0] += a.w * b.x; acc[3][1] += a.w * b.y; acc[3][2] += a.w * b.z; acc[3][3] += a.w * b.w;
        }
        __syncthreads();
    }

#pragma unroll
    for (int i = 0; i < 4; ++i)
#pragma unroll
        for (int j = 0; j < 4; ++j) {
            int m = m0 + ty * 4 + i;
            int n = n0 + tx * 4 + j;
            out[(size_t)m * Dm + n] = acc[i][j] + bias[n];
        }
}

// ---------------------------------------------------------------------------
extern "C" void kernel_launch(void* const* d_in, const int* in_sizes, int n_in,
                              void* d_out, int out_size)
{
    (void)in_sizes; (void)n_in; (void)out_size;
    const float* q    = (const float*)d_in[0];
    const float* k    = (const float*)d_in[1];
    const float* v    = (const float*)d_in[2];
    const float* Wq_w = (const float*)d_in[3];
    const float* Wq_b = (const float*)d_in[4];
    const float* Wc_w = (const float*)d_in[5];
    const float* Wc_b = (const float*)d_in[6];
    float* out = (float*)d_out;

    proj_kernel<<<dim3(Dm / 64, MROWS / 64, 3), 256>>>(q, k, v, Wq_w, Wq_b);
    qk_kernel<<<dim3(Sq / 64, Sq / 64, BHN), 256>>>();
    softmax_kernel<<<BHN * Sq, 256>>>();
    av_kernel<<<dim3(1, Sq / 64, BHN), 256>>>();
    outproj_kernel<<<dim3(Dm / 64, MROWS / 64), 256>>>(Wc_w, Wc_b, out);
}

// round 2
// speedup vs baseline: 1.7288x; 1.7288x over previous
#include <cuda_runtime.h>
#include <cstdint>

// Problem constants
#define Bsz    2
#define Sq     2048
#define Dm     512
#define Hn     8
#define DH     64
#define BHN    (Bsz*Hn)        // 16
#define MROWS  (Bsz*Sq)        // 4096

// Scratch (device globals — no allocation allowed in kernel_launch)
__device__ float g_qp[BHN * Sq * DH];   // [b,h,s,dh]  8 MB
__device__ float g_kp[BHN * Sq * DH];
__device__ float g_vp[BHN * Sq * DH];
__device__ float g_ctx[MROWS * Dm];     // merged-head context, 8 MB

// ---------------------------------------------------------------------------
// mma.sync m16n8k8 tf32 helper
// ---------------------------------------------------------------------------
__device__ __forceinline__ void mma_tf32(float* c, const uint32_t* a, const uint32_t* b)
{
    asm volatile(
        "mma.sync.aligned.m16n8k8.row.col.f32.tf32.tf32.f32 "
        "{%0,%1,%2,%3}, {%4,%5,%6,%7}, {%8,%9}, {%0,%1,%2,%3};\n"
        : "+f"(c[0]), "+f"(c[1]), "+f"(c[2]), "+f"(c[3])
        : "r"(a[0]), "r"(a[1]), "r"(a[2]), "r"(a[3]), "r"(b[0]), "r"(b[1]));
}

__device__ __forceinline__ uint32_t f2tf32(float x)
{
    uint32_t r;
    asm("cvt.rna.tf32.f32 %0, %1;" : "=r"(r) : "f"(x));
    return r;
}

__device__ __forceinline__ float fast_exp2(float x)
{
    float y;
    asm("ex2.approx.ftz.f32 %0, %1;" : "=f"(y) : "f"(x));
    return y;
}

// ---------------------------------------------------------------------------
// Kernel 1: fused QKV projection.  C = X @ W^T + b, written in [b,h,s,dh].
// (fp32 SIMT, unchanged from round 1 — known correct)
// ---------------------------------------------------------------------------
__global__ __launch_bounds__(256)
void proj_kernel(const float* __restrict__ q, const float* __restrict__ k,
                 const float* __restrict__ v, const float* __restrict__ W,
                 const float* __restrict__ bias)
{
    __shared__ float As[16][64];
    __shared__ float Bs[16][64];

    const float* X = (blockIdx.z == 0) ? q : (blockIdx.z == 1) ? k : v;
    float* out = (blockIdx.z == 0) ? g_qp : (blockIdx.z == 1) ? g_kp : g_vp;

    const int m0 = blockIdx.y * 64;
    const int n0 = blockIdx.x * 64;
    const int tid = threadIdx.x;
    const int tx = tid & 15, ty = tid >> 4;
    const int lm = tid >> 2, lk4 = (tid & 3) * 4;

    float acc[4][4] = {};

    for (int k0 = 0; k0 < Dm; k0 += 16) {
        float4 va = *(const float4*)(X + (size_t)(m0 + lm) * Dm + k0 + lk4);
        float4 vb = *(const float4*)(W + (size_t)(n0 + lm) * Dm + k0 + lk4);
        As[lk4 + 0][lm] = va.x; As[lk4 + 1][lm] = va.y;
        As[lk4 + 2][lm] = va.z; As[lk4 + 3][lm] = va.w;
        Bs[lk4 + 0][lm] = vb.x; Bs[lk4 + 1][lm] = vb.y;
        Bs[lk4 + 2][lm] = vb.z; Bs[lk4 + 3][lm] = vb.w;
        __syncthreads();
#pragma unroll
        for (int kk = 0; kk < 16; ++kk) {
            float4 a = *(const float4*)&As[kk][ty * 4];
            float4 b = *(const float4*)&Bs[kk][tx * 4];
            acc[0][0] += a.x * b.x; acc[0][1] += a.x * b.y; acc[0][2] += a.x * b.z; acc[0][3] += a.x * b.w;
            acc[1][0] += a.y * b.x; acc[1][1] += a.y * b.y; acc[1][2] += a.y * b.z; acc[1][3] += a.y * b.w;
            acc[2][0] += a.z * b.x; acc[2][1] += a.z * b.y; acc[2][2] += a.z * b.z; acc[2][3] += a.z * b.w;
            acc[3][0] += a.w * b.x; acc[3][1] += a.w * b.y; acc[3][2] += a.w * b.z; acc[3][3] += a.w * b.w;
        }
        __syncthreads();
    }

#pragma unroll
    for (int i = 0; i < 4; ++i) {
#pragma unroll
        for (int j = 0; j < 4; ++j) {
            int m = m0 + ty * 4 + i;       // b*2048+s
            int n = n0 + tx * 4 + j;       // h*64+d
            int b_ = m >> 11, s = m & 2047;
            int h  = n >> 6,  d = n & 63;
            out[(((size_t)(b_ * Hn + h) * Sq) + s) * DH + d] = acc[i][j] + bias[n];
        }
    }
}

// ---------------------------------------------------------------------------
// Kernel 2: fused flash attention (TF32 mma.sync + online softmax).
// grid = (Sq/64 = 32, BHN = 16), block = 128 threads (4 warps).
// Each warp owns 16 query rows; block processes BM=64 queries over all 2048
// keys in 32 tiles of 64.
// Smem: sK (K tile, later reused as P tile), sV (V tile, also Q staging).
// Row stride 72 floats -> conflict-free fragment LDS patterns.
// ---------------------------------------------------------------------------
#define KSTR 72

__global__ __launch_bounds__(128)
void flash_kernel()
{
    __shared__ uint32_t sK[64 * KSTR];   // K tile / P tile
    __shared__ uint32_t sV[64 * KSTR];   // V tile / Q staging

    const int z   = blockIdx.y;            // b*8 + h
    const int m0  = blockIdx.x * 64;
    const int tid = threadIdx.x;
    const int w   = tid >> 5;
    const int lane = tid & 31;
    const int g   = lane >> 2;             // group (row within fragment)
    const int t   = lane & 3;              // thread-in-group

    const float* Qg = g_qp + (size_t)z * Sq * DH;
    const float* Kg = g_kp + (size_t)z * Sq * DH;
    const float* Vg = g_vp + (size_t)z * Sq * DH;

    // scale folded into Q: 1/sqrt(64) * log2(e)  (softmax done in base-2)
    const float qscale = 0.125f * 1.44269504088896f;

    // --- stage Q tile into sV, extract persistent A fragments ---
    for (int i = tid; i < 64 * 16; i += 128) {
        int r = i >> 4, c = (i & 15) * 4;
        float4 v4 = *(const float4*)(Qg + (size_t)(m0 + r) * DH + c);
        sV[r * KSTR + c + 0] = f2tf32(v4.x * qscale);
        sV[r * KSTR + c + 1] = f2tf32(v4.y * qscale);
        sV[r * KSTR + c + 2] = f2tf32(v4.z * qscale);
        sV[r * KSTR + c + 3] = f2tf32(v4.w * qscale);
    }
    __syncthreads();

    uint32_t qf[8][4];
    {
        const int r0 = 16 * w + g;
#pragma unroll
        for (int kt = 0; kt < 8; ++kt) {
            qf[kt][0] = sV[r0 * KSTR + 8 * kt + t];
            qf[kt][1] = sV[(r0 + 8) * KSTR + 8 * kt + t];
            qf[kt][2] = sV[r0 * KSTR + 8 * kt + t + 4];
            qf[kt][3] = sV[(r0 + 8) * KSTR + 8 * kt + t + 4];
        }
    }
    __syncthreads();   // done reading Q staging; sV free for V tiles

    // --- running softmax state ---
    float o[8][4];
#pragma unroll
    for (int nt = 0; nt < 8; ++nt)
        o[nt][0] = o[nt][1] = o[nt][2] = o[nt][3] = 0.f;
    float m0s = -1e30f, m1s = -1e30f;   // row max (rows g, g+8 of band)
    float l0 = 0.f, l1 = 0.f;           // row sum

    for (int kb = 0; kb < Sq; kb += 64) {
        // load K and V tiles (converted to tf32 bits)
        for (int i = tid; i < 64 * 16; i += 128) {
            int r = i >> 4, c = (i & 15) * 4;
            float4 kv = *(const float4*)(Kg + (size_t)(kb + r) * DH + c);
            sK[r * KSTR + c + 0] = f2tf32(kv.x);
            sK[r * KSTR + c + 1] = f2tf32(kv.y);
            sK[r * KSTR + c + 2] = f2tf32(kv.z);
            sK[r * KSTR + c + 3] = f2tf32(kv.w);
            float4 vv = *(const float4*)(Vg + (size_t)(kb + r) * DH + c);
            sV[r * KSTR + c + 0] = f2tf32(vv.x);
            sV[r * KSTR + c + 1] = f2tf32(vv.y);
            sV[r * KSTR + c + 2] = f2tf32(vv.z);
            sV[r * KSTR + c + 3] = f2tf32(vv.w);
        }
        __syncthreads();

        // --- QK^T: scores c[nt][4], pre-scaled & in log2 domain ---
        float c[8][4];
#pragma unroll
        for (int nt = 0; nt < 8; ++nt)
            c[nt][0] = c[nt][1] = c[nt][2] = c[nt][3] = 0.f;

#pragma unroll
        for (int nt = 0; nt < 8; ++nt) {
            const uint32_t* kr = sK + (8 * nt + g) * KSTR + t;
#pragma unroll
            for (int kt = 0; kt < 8; ++kt) {
                uint32_t b[2] = { kr[8 * kt], kr[8 * kt + 4] };
                mma_tf32(c[nt], qf[kt], b);
            }
        }
        __syncthreads();   // everyone done reading sK; it becomes P tile

        // --- online softmax on fragments ---
        float tm0 = -1e30f, tm1 = -1e30f;
#pragma unroll
        for (int nt = 0; nt < 8; ++nt) {
            tm0 = fmaxf(tm0, fmaxf(c[nt][0], c[nt][1]));
            tm1 = fmaxf(tm1, fmaxf(c[nt][2], c[nt][3]));
        }
        tm0 = fmaxf(tm0, __shfl_xor_sync(0xffffffffu, tm0, 1));
        tm0 = fmaxf(tm0, __shfl_xor_sync(0xffffffffu, tm0, 2));
        tm1 = fmaxf(tm1, __shfl_xor_sync(0xffffffffu, tm1, 1));
        tm1 = fmaxf(tm1, __shfl_xor_sync(0xffffffffu, tm1, 2));

        float mn0 = fmaxf(m0s, tm0);
        float mn1 = fmaxf(m1s, tm1);
        float alpha0 = fast_exp2(m0s - mn0);
        float alpha1 = fast_exp2(m1s - mn1);
        m0s = mn0; m1s = mn1;

        const int r0 = 16 * w + g;
        float s0 = 0.f, s1 = 0.f;
#pragma unroll
        for (int nt = 0; nt < 8; ++nt) {
            float p0 = fast_exp2(c[nt][0] - mn0);
            float p1 = fast_exp2(c[nt][1] - mn0);
            float p2 = fast_exp2(c[nt][2] - mn1);
            float p3 = fast_exp2(c[nt][3] - mn1);
            uint32_t q0 = f2tf32(p0), q1 = f2tf32(p1);
            uint32_t q2 = f2tf32(p2), q3 = f2tf32(p3);
            s0 += __uint_as_float(q0) + __uint_as_float(q1);
            s1 += __uint_as_float(q2) + __uint_as_float(q3);
            int colo = 8 * nt + 2 * t;
            *(uint2*)&sK[r0 * KSTR + colo]       = make_uint2(q0, q1);
            *(uint2*)&sK[(r0 + 8) * KSTR + colo] = make_uint2(q2, q3);
        }
        s0 += __shfl_xor_sync(0xffffffffu, s0, 1);
        s0 += __shfl_xor_sync(0xffffffffu, s0, 2);
        s1 += __shfl_xor_sync(0xffffffffu, s1, 1);
        s1 += __shfl_xor_sync(0xffffffffu, s1, 2);
        l0 = l0 * alpha0 + s0;
        l1 = l1 * alpha1 + s1;

#pragma unroll
        for (int nt = 0; nt < 8; ++nt) {
            o[nt][0] *= alpha0; o[nt][1] *= alpha0;
            o[nt][2] *= alpha1; o[nt][3] *= alpha1;
        }
        __syncwarp();

        // --- P @ V accumulate ---
#pragma unroll
        for (int kt = 0; kt < 8; ++kt) {
            uint32_t a[4];
            a[0] = sK[r0 * KSTR + 8 * kt + t];
            a[1] = sK[(r0 + 8) * KSTR + 8 * kt + t];
            a[2] = sK[r0 * KSTR + 8 * kt + t + 4];
            a[3] = sK[(r0 + 8) * KSTR + 8 * kt + t + 4];
            const uint32_t* vr  = sV + (8 * kt + t) * KSTR + g;
            const uint32_t* vr4 = sV + (8 * kt + t + 4) * KSTR + g;
#pragma unroll
            for (int nt = 0; nt < 8; ++nt) {
                uint32_t b[2] = { vr[8 * nt], vr4[8 * nt] };
                mma_tf32(o[nt], a, b);
            }
        }
        __syncthreads();   // all warps done with sK (P) and sV before reload
    }

    // --- write O / l to merged-head context ---
    const float inv0 = 1.0f / l0;
    const float inv1 = 1.0f / l1;
    const int b_ = z >> 3, h = z & 7;
    const int row0 = m0 + 16 * w + g;
    const int row1 = row0 + 8;
#pragma unroll
    for (int nt = 0; nt < 8; ++nt) {
        int col = h * DH + 8 * nt + 2 * t;
        *(float2*)&g_ctx[(size_t)(b_ * Sq + row0) * Dm + col] =
            make_float2(o[nt][0] * inv0, o[nt][1] * inv0);
        *(float2*)&g_ctx[(size_t)(b_ * Sq + row1) * Dm + col] =
            make_float2(o[nt][2] * inv1, o[nt][3] * inv1);
    }
}

// ---------------------------------------------------------------------------
// Kernel 3: out = ctx @ Wc^T + bc.  (fp32 SIMT, unchanged)  grid = (8, 64)
// ---------------------------------------------------------------------------
__global__ __launch_bounds__(256)
void outproj_kernel(const float* __restrict__ W, const float* __restrict__ bias,
                    float* __restrict__ out)
{
    __shared__ float As[16][64];
    __shared__ float Bs[16][64];

    const int m0 = blockIdx.y * 64;
    const int n0 = blockIdx.x * 64;
    const int tid = threadIdx.x;
    const int tx = tid & 15, ty = tid >> 4;
    const int lm = tid >> 2, lk4 = (tid & 3) * 4;

    float acc[4][4] = {};

    for (int k0 = 0; k0 < Dm; k0 += 16) {
        float4 va = *(const float4*)(g_ctx + (size_t)(m0 + lm) * Dm + k0 + lk4);
        float4 vb = *(const float4*)(W + (size_t)(n0 + lm) * Dm + k0 + lk4);
        As[lk4 + 0][lm] = va.x; As[lk4 + 1][lm] = va.y;
        As[lk4 + 2][lm] = va.z; As[lk4 + 3][lm] = va.w;
        Bs[lk4 + 0][lm] = vb.x; Bs[lk4 + 1][lm] = vb.y;
        Bs[lk4 + 2][lm] = vb.z; Bs[lk4 + 3][lm] = vb.w;
        __syncthreads();
#pragma unroll
        for (int kk = 0; kk < 16; ++kk) {
            float4 a = *(const float4*)&As[kk][ty * 4];
            float4 b = *(const float4*)&Bs[kk][tx * 4];
            acc[0][0] += a.x * b.x; acc[0][1] += a.x * b.y; acc[0][2] += a.x * b.z; acc[0][3] += a.x * b.w;
            acc[1][0] += a.y * b.x; acc[1][1] += a.y * b.y; acc[1][2] += a.y * b.z; acc[1][3] += a.y * b.w;
            acc[2][0] += a.z * b.x; acc[2][1] += a.z * b.y; acc[2][2] += a.z * b.z; acc[2][3] += a.z * b.w;
            acc[3][0] += a.w * b.x; acc[3][1] += a.w * b.y; acc[3][2] += a.w * b.z; acc[3][3] += a.w * b.w;
        }
        __syncthreads();
    }

#pragma unroll
    for (int i = 0; i < 4; ++i)
#pragma unroll
        for (int j = 0; j < 4; ++j) {
            int m = m0 + ty * 4 + i;
            int n = n0 + tx * 4 + j;
            out[(size_t)m * Dm + n] = acc[i][j] + bias[n];
        }
}

// ---------------------------------------------------------------------------
extern "C" void kernel_launch(void* const* d_in, const int* in_sizes, int n_in,
                              void* d_out, int out_size)
{
    (void)in_sizes; (void)n_in; (void)out_size;
    const float* q    = (const float*)d_in[0];
    const float* k    = (const float*)d_in[1];
    const float* v    = (const float*)d_in[2];
    const float* Wq_w = (const float*)d_in[3];
    const float* Wq_b = (const float*)d_in[4];
    const float* Wc_w = (const float*)d_in[5];
    const float* Wc_b = (const float*)d_in[6];
    float* out = (float*)d_out;

    proj_kernel<<<dim3(Dm / 64, MROWS / 64, 3), 256>>>(q, k, v, Wq_w, Wq_b);
    flash_kernel<<<dim3(Sq / 64, BHN), 128>>>();
    outproj_kernel<<<dim3(Dm / 64, MROWS / 64), 256>>>(Wc_w, Wc_b, out);
}